// round 7
// baseline (speedup 1.0000x reference)
#include <cuda_runtime.h>
#include <math.h>
#include <stdint.h>

// ---------------------------------------------------------------------------
// Shapes (fixed)
// ---------------------------------------------------------------------------
#define Hd 1024
#define Fd 4096
#define Ed 8
#define Td 512
#define OUT_TOK 2048

// ---------------------------------------------------------------------------
// Static device scratch (allocation-free per harness rules)
// ---------------------------------------------------------------------------
__device__ float g_buf [Ed * Td * Hd];                  // dispatched acts (tf32-rounded)
__device__ float g_hmid[(size_t)Ed * Td * Fd];          // GEMM1+GELU out (tf32-rounded)
__device__ float g_obuf[Ed * Td * Hd];                  // GEMM2 out (fp32)
__device__ int   g_order[Td][Ed];
__device__ float g_score[Td][Ed];

// ---------------------------------------------------------------------------
// Helpers
// ---------------------------------------------------------------------------
__device__ __forceinline__ float tf32r(float x) {
    uint32_t u;
    asm("cvt.rna.tf32.f32 %0, %1;" : "=r"(u) : "f"(x));
    return __uint_as_float(u);
}
__device__ __forceinline__ void mma_tf32(float c[4], uint32_t a0, uint32_t a1,
                                         uint32_t a2, uint32_t a3,
                                         uint32_t b0, uint32_t b1) {
    asm volatile(
        "mma.sync.aligned.m16n8k8.row.col.f32.tf32.tf32.f32 "
        "{%0,%1,%2,%3}, {%4,%5,%6,%7}, {%8,%9}, {%0,%1,%2,%3};"
        : "+f"(c[0]), "+f"(c[1]), "+f"(c[2]), "+f"(c[3])
        : "r"(a0), "r"(a1), "r"(a2), "r"(a3), "r"(b0), "r"(b1));
}
__device__ __forceinline__ float gelu_exact(float v) {
    return 0.5f * v * (1.0f + erff(v * 0.70710678118654752f));
}

// ---------------------------------------------------------------------------
// Gating
// ---------------------------------------------------------------------------
__global__ void gate_kernel(const float* __restrict__ x,
                            const float* __restrict__ Wg,
                            const float* __restrict__ bg) {
    int warp = threadIdx.x >> 5;
    int lane = threadIdx.x & 31;
    int t = blockIdx.x * 8 + warp;
    if (t >= Td) return;

    const float* xr = x + (size_t)t * Hd;
    float acc[Ed];
#pragma unroll
    for (int e = 0; e < Ed; e++) acc[e] = 0.f;
    for (int h = lane; h < Hd; h += 32) {
        float xv = xr[h];
        const float* wr = Wg + (size_t)h * Ed;
#pragma unroll
        for (int e = 0; e < Ed; e++) acc[e] += xv * wr[e];
    }
#pragma unroll
    for (int e = 0; e < Ed; e++) {
#pragma unroll
        for (int o = 16; o > 0; o >>= 1)
            acc[e] += __shfl_xor_sync(0xffffffffu, acc[e], o);
    }
    if (lane == 0) {
        float l[Ed], p[Ed];
        float mx = -1e30f;
#pragma unroll
        for (int e = 0; e < Ed; e++) { l[e] = acc[e] + bg[e]; mx = fmaxf(mx, l[e]); }
        float s = 0.f;
#pragma unroll
        for (int e = 0; e < Ed; e++) { p[e] = expf(l[e] - mx); s += p[e]; }
#pragma unroll
        for (int e = 0; e < Ed; e++) p[e] /= s;
        float sum = 0.f;
#pragma unroll
        for (int e = 0; e < Ed; e++) sum += p[e];
        float inv = 1.0f / (sum + 1e-9f);
        bool used[Ed];
#pragma unroll
        for (int e = 0; e < Ed; e++) used[e] = false;
        for (int r = 0; r < Ed; r++) {
            int best = -1; float bv = -1e30f;
            for (int e = 0; e < Ed; e++)
                if (!used[e] && p[e] > bv) { bv = p[e]; best = e; }
            used[best] = true;
            g_order[t][r] = best;
            g_score[t][r] = bv * inv;
        }
    }
}

// ---------------------------------------------------------------------------
// Dispatch (tf32-rounds the MMA A operand)
// ---------------------------------------------------------------------------
__global__ void dispatch_kernel(const float* __restrict__ x) {
    int t = blockIdx.x;
    int r = blockIdx.y;
    int e = g_order[t][r];
    float sc = g_score[t][r];
    int src = 4 * t + (r >> 1);
    const float4* xs = (const float4*)(x + (size_t)src * Hd);
    float4* dst = (float4*)(g_buf + ((size_t)e * Td + t) * Hd);
    float4 v = xs[threadIdx.x];
    v.x = tf32r(v.x * sc); v.y = tf32r(v.y * sc);
    v.z = tf32r(v.z * sc); v.w = tf32r(v.w * sc);
    dst[threadIdx.x] = v;
}

// ---------------------------------------------------------------------------
// tf32 mma.sync GEMM with FRAGMENT-MAJOR SMEM layout.
//
// Both operands stored per 128x16 tile as:
//   S[row][ (g ^ ((row>>1)&3)) * 4 + c ]  <-  V[row][k],  g = k&3, c = k>>2
// so one LDS.128 at (row, tg) yields {V[row][tg], V[row][tg+4], V[row][tg+8],
// V[row][tg+12]} = exactly the 4 k-words one thread needs for BOTH k-halves
// of an m16n8k8 pair.  12 LDS.128 per warp-iter replace 48 LDS.32.
// XOR swizzle makes reads AND writes bank-conflict-free.
//
// BM=128 BN=128 BK=16, 3-stage LDG->reg->STS pipeline for both operands.
// ---------------------------------------------------------------------------
#define AWORDS (128 * 16)                    // words per stage (8 KB)
#define GEMM_SMEM_BYTES (6 * AWORDS * 4)     // A:3 stages + B:3 stages = 48 KB

template <int Kdim, int Ndim, bool DoGelu>
__global__ __launch_bounds__(256, 2)
void gemm_mma(const float* __restrict__ A_, const float* __restrict__ B_,
              const float* __restrict__ bias_, float* __restrict__ C_) {
    constexpr int BK = 16;
    constexpr int NK = Kdim / BK;

    extern __shared__ float smem[];
    float* AsB = smem;                  // [3][128][16]
    float* BsB = smem + 3 * AWORDS;     // [3][128][16]

    const int e  = blockIdx.z;
    const int m0 = blockIdx.y * 128;
    const int n0 = blockIdx.x * 128;
    const int tid = threadIdx.x;

    const float* Ag = A_ + (size_t)e * Td * Kdim;
    const float* Bg = B_ + (size_t)e * Kdim * Ndim;   // [K][N] row-major

    // ---- A loader: thread = (row_a, j_a); LDG.128 x2 (k-contiguous), then
    //      permuted STS.64 x4 into fragment-major layout ----
    const int row_a = tid >> 1;
    const int j_a   = tid & 1;
    const int swA   = (row_a >> 1) & 3;
    const float* gA0 = Ag + (size_t)(m0 + row_a) * Kdim + j_a * 8;
    float rA[8];

    auto ldgA = [&](int i) {
        float4 u = *(const float4*)(gA0 + i * BK);
        float4 v = *(const float4*)(gA0 + i * BK + 4);
        rA[0] = u.x; rA[1] = u.y; rA[2] = u.z; rA[3] = u.w;
        rA[4] = v.x; rA[5] = v.y; rA[6] = v.z; rA[7] = v.w;
    };
    auto stsA = [&](int i) {
        float* p = AsB + (i % 3) * AWORDS + row_a * 16 + j_a * 2;
#pragma unroll
        for (int ii = 0; ii < 4; ii++)     // k=8j+ii -> c=2j ; k=8j+4+ii -> c=2j+1
            *(float2*)(p + ((ii ^ swA) << 2)) = make_float2(rA[ii], rA[ii + 4]);
    };

    // ---- B loader: thread = (n_b, gp); strided LDG.32 x8 (transpose + tf32
    //      round), then STS.128 x2 into fragment-major layout ----
    const int n_b = tid >> 1;
    const int gp  = tid & 1;
    const int swB = (n_b >> 1) & 3;
    const float* gB0 = Bg + n0 + n_b;
    float rB[8];

    auto ldgB = [&](int i) {
#pragma unroll
        for (int q = 0; q < 2; q++) {
            int g = 2 * gp + q;
#pragma unroll
            for (int cc = 0; cc < 4; cc++)
                rB[q * 4 + cc] = tf32r(gB0[(size_t)(i * BK + g + 4 * cc) * Ndim]);
        }
    };
    auto stsB = [&](int i) {
        float* p = BsB + (i % 3) * AWORDS + n_b * 16;
#pragma unroll
        for (int q = 0; q < 2; q++) {
            int g = 2 * gp + q;
            *(float4*)(p + (((g ^ swB)) << 2)) = *(const float4*)&rB[q * 4];
        }
    };

    // ---- warp/fragment mapping ----
    const int wid  = tid >> 5;
    const int lane = tid & 31;
    const int wm = wid >> 2;                 // 0..1
    const int wn = wid & 3;                  // 0..3
    const int grp = lane >> 2;               // 0..7
    const int tg  = lane & 3;                // 0..3
    const int fragoff = ((tg ^ ((grp >> 1) & 3)) << 2);   // swizzled k-group offset

    float c[4][4][4];
#pragma unroll
    for (int mt = 0; mt < 4; mt++)
#pragma unroll
        for (int nt = 0; nt < 4; nt++)
#pragma unroll
            for (int q = 0; q < 4; q++) c[mt][nt][q] = 0.f;

    // prologue: stages 0,1 stored; stage 2 held in regs (STS at iter-0 top)
    ldgA(0); ldgB(0); stsA(0); stsB(0);
    ldgA(1); ldgB(1); stsA(1); stsB(1);
    ldgA(2); ldgB(2);

    for (int i = 0; i < NK; i++) {
        __syncthreads();
        // stage (i+2)%3 == (i-1)%3: finished being read before the barrier
        if (i + 2 < NK) { stsA(i + 2); stsB(i + 2); }
        if (i + 3 < NK) { ldgA(i + 3); ldgB(i + 3); }

        const float* as = AsB + (i % 3) * AWORDS;
        const float* bs = BsB + (i % 3) * AWORDS;

        uint4 qb[4];
#pragma unroll
        for (int nt = 0; nt < 4; nt++) {
            int cn = wn * 32 + nt * 8 + grp;
            qb[nt] = *(const uint4*)(bs + cn * 16 + fragoff);
        }
#pragma unroll
        for (int mt = 0; mt < 4; mt++) {
            int r = wm * 64 + mt * 16 + grp;
            uint4 q1 = *(const uint4*)(as + r * 16 + fragoff);        // row r
            uint4 q2 = *(const uint4*)(as + (r + 8) * 16 + fragoff);  // row r+8
#pragma unroll
            for (int nt = 0; nt < 4; nt++) {
                // kk = 0 : k in [0,8)
                mma_tf32(c[mt][nt], q1.x, q2.x, q1.y, q2.y, qb[nt].x, qb[nt].y);
                // kk = 1 : k in [8,16)
                mma_tf32(c[mt][nt], q1.z, q2.z, q1.w, q2.w, qb[nt].z, qb[nt].w);
            }
        }
    }

    // Epilogue: bias (+GELU +tf32 round), float2 stores
    const float* bias = bias_ + (size_t)e * Ndim + n0;
    float* C = C_ + (size_t)e * Td * Ndim;
#pragma unroll
    for (int mt = 0; mt < 4; mt++) {
        int r0 = m0 + wm * 64 + mt * 16 + grp;
#pragma unroll
        for (int nt = 0; nt < 4; nt++) {
            int col = wn * 32 + nt * 8 + tg * 2;
            float bx = bias[col], by = bias[col + 1];
            float2 v0, v1;
            v0.x = c[mt][nt][0] + bx;  v0.y = c[mt][nt][1] + by;
            v1.x = c[mt][nt][2] + bx;  v1.y = c[mt][nt][3] + by;
            if (DoGelu) {
                v0.x = tf32r(gelu_exact(v0.x)); v0.y = tf32r(gelu_exact(v0.y));
                v1.x = tf32r(gelu_exact(v1.x)); v1.y = tf32r(gelu_exact(v1.y));
            }
            *(float2*)(C + (size_t)r0 * Ndim + n0 + col) = v0;
            *(float2*)(C + (size_t)(r0 + 8) * Ndim + n0 + col) = v1;
        }
    }
}

// ---------------------------------------------------------------------------
// Combine
// ---------------------------------------------------------------------------
__global__ void combine_kernel(float* __restrict__ out) {
    int m = blockIdx.x;
    int t = m >> 2;
    int q = m & 3;
    int e1 = g_order[t][2 * q];
    int e2 = g_order[t][2 * q + 1];
    const float4* o1 = (const float4*)(g_obuf + ((size_t)e1 * Td + t) * Hd);
    const float4* o2 = (const float4*)(g_obuf + ((size_t)e2 * Td + t) * Hd);
    float4* dst = (float4*)(out + (size_t)m * Hd);
    float4 a = o1[threadIdx.x];
    float4 b = o2[threadIdx.x];
    float4 v; v.x = a.x + b.x; v.y = a.y + b.y; v.z = a.z + b.z; v.w = a.w + b.w;
    dst[threadIdx.x] = v;
}

// ---------------------------------------------------------------------------
extern "C" void kernel_launch(void* const* d_in, const int* in_sizes, int n_in,
                              void* d_out, int out_size) {
    (void)in_sizes; (void)n_in;
    const float* x  = (const float*)d_in[0];
    const float* Wg = (const float*)d_in[1];
    const float* bg = (const float*)d_in[2];
    const float* W1 = (const float*)d_in[3];
    const float* b1 = (const float*)d_in[4];
    const float* W2 = (const float*)d_in[5];
    const float* b2 = (const float*)d_in[6];
    float* out = (float*)d_out;

    float *buf, *hmid, *obuf;
    cudaGetSymbolAddress((void**)&buf,  g_buf);
    cudaGetSymbolAddress((void**)&hmid, g_hmid);
    cudaGetSymbolAddress((void**)&obuf, g_obuf);

    cudaFuncSetAttribute(gemm_mma<Hd, Fd, true>,
                         cudaFuncAttributeMaxDynamicSharedMemorySize, GEMM_SMEM_BYTES);
    cudaFuncSetAttribute(gemm_mma<Fd, Hd, false>,
                         cudaFuncAttributeMaxDynamicSharedMemorySize, GEMM_SMEM_BYTES);

    // Output tail (batches 1-3 + aux-loss scalar, all exactly zero)
    size_t nz = (size_t)OUT_TOK * Hd;
    cudaMemsetAsync(out + nz, 0, ((size_t)out_size - nz) * sizeof(float), 0);

    gate_kernel<<<Td / 8, 256>>>(x, Wg, bg);
    dispatch_kernel<<<dim3(Td, Ed), 256>>>(x);

    // GEMM1 + GELU: per expert (512 x 1024) @ (1024 x 4096), B in native layout
    gemm_mma<Hd, Fd, true><<<dim3(Fd / 128, Td / 128, Ed), 256, GEMM_SMEM_BYTES>>>(buf, W1, b1, hmid);
    // GEMM2: per expert (512 x 4096) @ (4096 x 1024), B in native layout
    gemm_mma<Fd, Hd, false><<<dim3(Hd / 128, Td / 128, Ed), 256, GEMM_SMEM_BYTES>>>(hmid, W2, b2, obuf);

    combine_kernel<<<OUT_TOK, 256>>>(out);
}